// round 8
// baseline (speedup 1.0000x reference)
#include <cuda_runtime.h>
#include <cstdint>

#define BATCH 4096

// ---------------- device-global staging (written by pre-kernel) ----------------
// gWimg: int8 B fragment image, direct mma-register order.
//   [chunk 8][nhalf 2][ng 4][kb 4][lane 32][16B = {b0p0,b1p0,b0p1,b1p1}]
//   lane l (g=l>>2, t=l&3): fragment col = g, k rows b0: kb*32+4t+0..3, b1: +16.
//   Column permutation: global col for (nhalf, ng, in-tile col j):
//     chunk*64 + nhalf*32 + (ng>>1)*16 + 4*(j>>1) + 2*(ng&1) + (j&1)
//   => epilogue thread t owns 4-contiguous col groups (float4 stores).
__device__ __align__(1024) unsigned char gWimg[131072];
// gT[half][f][h] = sum_c Wlin[f][c] * Watt[(half*512 + c)*8 + h]
__device__ __align__(16) float gT[2][128][8];

// ---------------- PTX helpers ----------------
__device__ __forceinline__ uint32_t smem_u32(const void* p) {
    uint32_t a;
    asm("{ .reg .u64 t; cvta.to.shared.u64 t, %1; cvt.u32.u64 %0, t; }" : "=r"(a) : "l"(p));
    return a;
}
__device__ __forceinline__ void cp_async16(uint32_t saddr, const void* g) {
    asm volatile("cp.async.cg.shared.global [%0], [%1], 16;" :: "r"(saddr), "l"(g));
}
__device__ __forceinline__ void cp_commit() { asm volatile("cp.async.commit_group;"); }
template<int N> __device__ __forceinline__ void cp_wait() {
    asm volatile("cp.async.wait_group %0;" :: "n"(N));
}

__device__ __forceinline__ void mmas8(int* c, const uint32_t* a, uint32_t b0, uint32_t b1) {
    asm("mma.sync.aligned.m16n8k32.row.col.s32.s8.s8.s32 "
        "{%0,%1,%2,%3},{%4,%5,%6,%7},{%8,%9},{%0,%1,%2,%3};"
        : "+r"(c[0]), "+r"(c[1]), "+r"(c[2]), "+r"(c[3])
        : "r"(a[0]), "r"(a[1]), "r"(a[2]), "r"(a[3]), "r"(b0), "r"(b1));
}

// ---------------- quantization ----------------
__device__ __forceinline__ int clamp127(int v) { return max(-127, min(127, v)); }
__device__ __forceinline__ uint32_t pk4(int a, int b, int c, int d) {
    return (a & 255) | ((b & 255) << 8) | ((c & 255) << 16) | ((d & 255) << 24);
}
// x = q0/16 + q1/4096 + eps(<=1.3e-4)
__device__ __forceinline__ void quant_x(float v, int& q0, int& q1) {
    q0 = __float2int_rn(v * 16.f);
    float r = v - (float)q0 * 0.0625f;
    q1 = clamp127(__float2int_rn(r * 4096.f));
}
__device__ __forceinline__ void quant4x(float4 v, uint32_t& q0w, uint32_t& q1w) {
    int a0, a1, b0, b1, c0, c1, d0, d1;
    quant_x(v.x, a0, a1); quant_x(v.y, b0, b1);
    quant_x(v.z, c0, c1); quant_x(v.w, d0, d1);
    q0w = pk4(a0, b0, c0, d0); q1w = pk4(a1, b1, c1, d1);
}
// w = p0/256 + p1/65536 + eps(<=8e-6)
__device__ __forceinline__ void quant_w(float v, int& p0, int& p1) {
    p0 = clamp127(__float2int_rn(v * 256.f));
    float r = v - (float)p0 * (1.f / 256.f);
    p1 = clamp127(__float2int_rn(r * 65536.f));
}

// ---------------- fused pre-kernel ----------------
// blocks [0,32): B image (8192 threads, one 16B fragment slot each)
// blocks [32,96): T = Wlin @ Watt halves (shfl-reduced)
__global__ void k_prep(const float* __restrict__ Wlin, const float* __restrict__ Watt) {
    int blk = blockIdx.x;
    if (blk < 32) {
        int id = blk * 256 + threadIdx.x;          // 0..8191
        int l = id & 31, kb = (id >> 5) & 3, ng = (id >> 7) & 3;
        int nhalf = (id >> 9) & 1, chunk = id >> 10;
        int g = l >> 2, t = l & 3;
        int n = chunk * 64 + nhalf * 32 + (ng >> 1) * 16 + 4 * (g >> 1)
              + 2 * (ng & 1) + (g & 1);
        int p0[8], p1[8];
        #pragma unroll
        for (int k = 0; k < 4; ++k) {
            int kk = kb * 32 + 4 * t + k;
            quant_w(Wlin[(size_t)kk * 512 + n],        p0[k],     p1[k]);
            quant_w(Wlin[(size_t)(kk + 16) * 512 + n], p0[4 + k], p1[4 + k]);
        }
        uint4 frag;
        frag.x = pk4(p0[0], p0[1], p0[2], p0[3]);   // b0p0
        frag.y = pk4(p0[4], p0[5], p0[6], p0[7]);   // b1p0
        frag.z = pk4(p1[0], p1[1], p1[2], p1[3]);   // b0p1
        frag.w = pk4(p1[4], p1[5], p1[6], p1[7]);   // b1p1
        ((uint4*)gWimg)[id] = frag;
    } else {
        int t = (blk - 32) * 256 + threadIdx.x;     // 0..16383
        int o = t >> 3, sub = t & 7;
        int half = o >> 10, f = (o >> 3) & 127, h = o & 7;
        const float* wl = Wlin + (size_t)f * 512;
        const float* wa = Watt + (size_t)half * 512 * 8 + h;
        float acc = 0.f;
        int c0 = sub * 64;
        #pragma unroll 8
        for (int c = c0; c < c0 + 64; ++c)
            acc += wl[c] * wa[(size_t)c * 8];
        #pragma unroll
        for (int off = 4; off > 0; off >>= 1)
            acc += __shfl_xor_sync(0xffffffffu, acc, off);
        if (sub == 0) gT[half][f][h] = acc;
    }
}

// ---------------- main kernel: 256 threads, 1 batch, 2 CTAs/SM ----------------
// SMEM: A frag image [mblk4][kb4][word2][lane32][16B] @0 (16KB)
//       B ring 3 x 16KB @16384 (x fp32 stage [64][128]=32KB aliased on buf0+buf1)
//       SS[8] @65536 ; ATT[8][64] @65568 ; T copy @67616 (8KB)
#define SM_A     0
#define SM_B     16384
#define SM_SS    65536
#define SM_ATT   65568
#define SM_T     67616
#define SMEM_BYTES (SM_T + 8192)

__global__ void __launch_bounds__(256, 2)
agg_main(const float* __restrict__ x, const int* __restrict__ mask,
         float* __restrict__ out)
{
    extern __shared__ unsigned char sm[];
    const int t = threadIdx.x, w = t >> 5, lane = t & 31;
    const int b = blockIdx.x;
    const uint32_t sb = smem_u32(sm);
    float* stage = (float*)(sm + SM_B);            // aliased on B buf0+buf1
    float* attb  = (float*)(sm + SM_ATT);
    float* sS    = (float*)(sm + SM_SS);
    const float* sT0 = (float*)(sm + SM_T);
    const float* sT1 = (float*)(sm + SM_T) + 128 * 8;

    // ---- G0: x (32KB) + T (8KB) ----
    const float* xp = x + (size_t)b * 8192;
    #pragma unroll
    for (int i = 0; i < 8; ++i) {
        int idx = t + i * 256;
        cp_async16(sb + SM_B + idx * 16, (const char*)xp + idx * 16);
    }
    #pragma unroll
    for (int i = 0; i < 2; ++i) {
        int idx = t + i * 256;
        cp_async16(sb + SM_T + idx * 16, (const char*)gT + idx * 16);
    }
    cp_commit();
    // ---- G1: chunk 0 -> buf2 (free region) ----
    #pragma unroll
    for (int i = 0; i < 4; ++i) {
        int u = t + i * 256;
        cp_async16(sb + SM_B + 32768u + u * 16, &gWimg[u * 16]);
    }
    cp_commit();
    cp_wait<1>();       // x + T arrived
    __syncthreads();

    // ---- convert x -> int8 A fragment image (q0/q1) ----
    #pragma unroll
    for (int s = 0; s < 2; ++s) {
        int slot = t + s * 256;                    // 512 slots
        int l = slot & 31, kb = (slot >> 5) & 3, mb = slot >> 7;
        int g = l >> 2, q = l & 3;
        const float* r0p = stage + (mb * 16 + g) * 128 + kb * 32 + q * 4;
        float4 xa = *(float4*)(r0p);
        float4 xb = *(float4*)(r0p + 16);
        float4 xc = *(float4*)(r0p + 8 * 128);
        float4 xd = *(float4*)(r0p + 8 * 128 + 16);
        uint32_t a0q0, a0q1, a1q0, a1q1, a2q0, a2q1, a3q0, a3q1;
        quant4x(xa, a0q0, a0q1);   // a0: row g,   k 4q..+3
        quant4x(xc, a1q0, a1q1);   // a1: row g+8
        quant4x(xb, a2q0, a2q1);   // a2: row g,   k+16
        quant4x(xd, a3q0, a3q1);   // a3: row g+8, k+16
        uint32_t base = (uint32_t)((mb * 4 + kb) * 2) * 512u + (uint32_t)l * 16u;
        *(uint4*)(sm + SM_A + base)        = make_uint4(a0q0, a1q0, a2q0, a3q0);
        *(uint4*)(sm + SM_A + base + 512u) = make_uint4(a0q1, a1q1, a2q1, a3q1);
    }

    // ---- attention logits: 512 (r,h) tasks, fp32 from stage ----
    float dotv[2]; int rr2[2], hh2[2];
    #pragma unroll
    for (int j = 0; j < 2; ++j) {
        int idx2 = t + j * 256;
        int r = idx2 >> 3, h = idx2 & 7;
        const float* xr = stage + r * 128;
        float acc = 0.f;
        #pragma unroll 4
        for (int k = 0; k < 128; k += 4) {
            float4 xv = *(float4*)(xr + k);
            acc += xv.x * sT1[(k + 0) * 8 + h];
            acc += xv.y * sT1[(k + 1) * 8 + h];
            acc += xv.z * sT1[(k + 2) * 8 + h];
            acc += xv.w * sT1[(k + 3) * 8 + h];
        }
        dotv[j] = acc; rr2[j] = r; hh2[j] = h;
    }
    float srcv = 0.f;
    if (t < 8) {        // src term: row 0 vs T0, head = t
        const float* xr = stage;
        #pragma unroll 4
        for (int k = 0; k < 128; k += 4) {
            float4 xv = *(float4*)(xr + k);
            srcv += xv.x * sT0[(k + 0) * 8 + t];
            srcv += xv.y * sT0[(k + 1) * 8 + t];
            srcv += xv.z * sT0[(k + 2) * 8 + t];
            srcv += xv.w * sT0[(k + 3) * 8 + t];
        }
    }
    __syncthreads();    // stage fully read; A image complete
    if (t < 8) sS[t] = srcv;

    // ---- G2: chunk 1 -> buf0 (stage dead) ----
    #pragma unroll
    for (int i = 0; i < 4; ++i) {
        int u = t + i * 256;
        cp_async16(sb + SM_B + u * 16, &gWimg[16384 + u * 16]);
    }
    cp_commit();

    // ---- hoist A fragments (chunk-invariant): 32 regs ----
    const int mblk = w >> 1, nhalf = w & 1;
    uint32_t aq0[4][4], aq1[4][4];
    #pragma unroll
    for (int kb = 0; kb < 4; ++kb) {
        uint32_t base = (uint32_t)((mblk * 4 + kb) * 2) * 512u + (uint32_t)lane * 16u;
        *(uint4*)aq0[kb] = *(const uint4*)(sm + SM_A + base);
        *(uint4*)aq1[kb] = *(const uint4*)(sm + SM_A + base + 512u);
    }
    __syncthreads();    // sS visible

    // ---- logits -> attb ----
    #pragma unroll
    for (int j = 0; j < 2; ++j) {
        int n = rr2[j];
        float v = sS[hh2[j]] + dotv[j];
        v = (v >= 0.f) ? v : 0.2f * v;
        attb[hh2[j] * 64 + n] = v;
    }
    __syncthreads();

    // ---- softmax: warp w -> head w ----
    {
        int m0 = mask[b * 64 + lane];
        int m1 = mask[b * 64 + lane + 32];
        float v0 = attb[w * 64 + lane]      + (m0 == 0 ? -1e9f : 0.f);
        float v1 = attb[w * 64 + lane + 32] + (m1 == 0 ? -1e9f : 0.f);
        float mx = fmaxf(v0, v1);
        #pragma unroll
        for (int o = 16; o > 0; o >>= 1) mx = fmaxf(mx, __shfl_xor_sync(0xffffffffu, mx, o));
        float e0 = __expf(v0 - mx), e1 = __expf(v1 - mx);
        float sum = e0 + e1;
        #pragma unroll
        for (int o = 16; o > 0; o >>= 1) sum += __shfl_xor_sync(0xffffffffu, sum, o);
        float inv = 1.f / sum;
        attb[w * 64 + lane]      = e0 * inv;
        attb[w * 64 + lane + 32] = e1 * inv;
    }

    // ---- epilogue lane mapping ----
    const int eg = lane >> 2, eq = lane & 3;
    const int row0 = mblk * 16 + eg;
    float* obase = out + ((size_t)b * 64 + row0) * 512 + nhalf * 32 + eq * 4;

    // ---- mainloop: 8 chunks (chunk == head), 3-stage B ring ----
    // chunk c in buf (c+2)%3; iter c issues chunk c+2 into buf (c+1)%3
    for (int c = 0; c < 8; ++c) {
        if (c < 7) cp_wait<1>(); else cp_wait<0>();   // chunk c arrived
        __syncthreads();
        if (c + 2 <= 7) {
            uint32_t dst = sb + SM_B + (uint32_t)((c + 1) % 3) * 16384u;
            #pragma unroll
            for (int i = 0; i < 4; ++i) {
                int u = t + i * 256;
                cp_async16(dst + u * 16, &gWimg[(c + 2) * 16384 + u * 16]);
            }
            cp_commit();
        }

        const unsigned char* bbuf = sm + SM_B + (uint32_t)((c + 2) % 3) * 16384u;
        int ah[16], am[16], al[16];
        #pragma unroll
        for (int i = 0; i < 16; ++i) { ah[i] = 0; am[i] = 0; al[i] = 0; }

        #pragma unroll
        for (int kb = 0; kb < 4; ++kb) {
            uint4 bb[4];
            #pragma unroll
            for (int ng = 0; ng < 4; ++ng)
                bb[ng] = *(const uint4*)(bbuf
                         + (uint32_t)((nhalf * 16 + ng * 4 + kb) * 32 + lane) * 16u);
            #pragma unroll
            for (int ng = 0; ng < 4; ++ng) {
                mmas8(ah + ng * 4, aq0[kb], bb[ng].x, bb[ng].y);   // q0 p0
                mmas8(am + ng * 4, aq0[kb], bb[ng].z, bb[ng].w);   // q0 p1
                mmas8(am + ng * 4, aq1[kb], bb[ng].x, bb[ng].y);   // q1 p0
                mmas8(al + ng * 4, aq1[kb], bb[ng].z, bb[ng].w);   // q1 p1
            }
        }

        // ---- epilogue: combine scales, aw, relu, 4x STG.128 ----
        float sc0 = attb[c * 64 + row0];
        float sc1 = attb[c * 64 + row0 + 8];
        float fv[16];
        #pragma unroll
        for (int i = 0; i < 16; ++i) {
            int ml = am[i] + (al[i] >> 8);
            fv[i] = (float)ah[i] * 0x1p-12f + (float)ml * 0x1p-20f;
        }
        float* o = obase + c * 64;
        float4 v00 = make_float4(fmaxf(fv[0] * sc0, 0.f),  fmaxf(fv[1] * sc0, 0.f),
                                 fmaxf(fv[4] * sc0, 0.f),  fmaxf(fv[5] * sc0, 0.f));
        float4 v01 = make_float4(fmaxf(fv[8] * sc0, 0.f),  fmaxf(fv[9] * sc0, 0.f),
                                 fmaxf(fv[12] * sc0, 0.f), fmaxf(fv[13] * sc0, 0.f));
        float4 v10 = make_float4(fmaxf(fv[2] * sc1, 0.f),  fmaxf(fv[3] * sc1, 0.f),
                                 fmaxf(fv[6] * sc1, 0.f),  fmaxf(fv[7] * sc1, 0.f));
        float4 v11 = make_float4(fmaxf(fv[10] * sc1, 0.f), fmaxf(fv[11] * sc1, 0.f),
                                 fmaxf(fv[14] * sc1, 0.f), fmaxf(fv[15] * sc1, 0.f));
        *(float4*)(o)              = v00;
        *(float4*)(o + 16)         = v01;
        *(float4*)(o + 4096)       = v10;   // row +8
        *(float4*)(o + 4096 + 16)  = v11;
    }
}

// ---------------- launch ----------------
extern "C" void kernel_launch(void* const* d_in, const int* in_sizes, int n_in,
                              void* d_out, int out_size)
{
    const float* x    = (const float*)d_in[0];
    const float* Wlin = (const float*)d_in[1];
    const float* Watt = (const float*)d_in[2];
    const int*   mk   = (const int*)d_in[3];
    float*       out  = (float*)d_out;

    k_prep<<<96, 256>>>(Wlin, Watt);

    cudaFuncSetAttribute(agg_main, cudaFuncAttributeMaxDynamicSharedMemorySize, SMEM_BYTES);
    agg_main<<<BATCH, 256, SMEM_BYTES>>>(x, mk, out);
}

// round 9
// speedup vs baseline: 3.7296x; 3.7296x over previous
#include <cuda_runtime.h>
#include <cuda_fp16.h>
#include <cstdint>

#define BATCH 4096

// ---------------- device-global staging (written by pre-kernel) ----------------
// gWimg: fp16 B ldmatrix image, [chunk 8][nblk 8][kblk 8][tile 256B]
//   tile = 8 n-slots x 16 k fp16, slot nr at ((nr*32 + kh*16) ^ ((nr&4)?16:0)) + (k&7)*2
//   N-permutation (contiguous epilogue stores):
//     chunk=n>>6, cc=n&63, nhalf=cc>>5, w32=cc&31, j=w32>>3, g=(w32>>1)&3, r=w32&1
//     nblk = nhalf*4 + g ; slot = 2j + r
__device__ __align__(1024) unsigned char gWimg[131072];
// gT[half][f][h] = sum_c Wlin[f][c] * Watt[(half*512 + c)*8 + h]  (read via L1/L2 in-kernel)
__device__ __align__(16) float gT[2][128][8];

// ---------------- PTX helpers ----------------
__device__ __forceinline__ uint32_t smem_u32(const void* p) {
    uint32_t a;
    asm("{ .reg .u64 t; cvta.to.shared.u64 t, %1; cvt.u32.u64 %0, t; }" : "=r"(a) : "l"(p));
    return a;
}
__device__ __forceinline__ void cp_async16(uint32_t saddr, const void* g) {
    asm volatile("cp.async.cg.shared.global [%0], [%1], 16;" :: "r"(saddr), "l"(g));
}
__device__ __forceinline__ void cp_commit() { asm volatile("cp.async.commit_group;"); }
template<int N> __device__ __forceinline__ void cp_wait() {
    asm volatile("cp.async.wait_group %0;" :: "n"(N));
}

#define LDSM_X4(d, a)                                                             \
    asm volatile("ldmatrix.sync.aligned.m8n8.x4.shared.b16 {%0,%1,%2,%3}, [%4];"  \
        : "=r"((d)[0]), "=r"((d)[1]), "=r"((d)[2]), "=r"((d)[3]) : "r"(a))

__device__ __forceinline__ void mmaf16(float* c, const uint32_t* a,
                                       uint32_t b0, uint32_t b1) {
    asm volatile("mma.sync.aligned.m16n8k16.row.col.f32.f16.f16.f32 "
        "{%0,%1,%2,%3}, {%4,%5,%6,%7}, {%8,%9}, {%0,%1,%2,%3};"
        : "+f"(c[0]), "+f"(c[1]), "+f"(c[2]), "+f"(c[3])
        : "r"(a[0]), "r"(a[1]), "r"(a[2]), "r"(a[3]), "r"(b0), "r"(b1));
}

__device__ __forceinline__ uint32_t pkh2(float a, float b) {
    __half2 t = __floats2half2_rn(a, b);
    return *reinterpret_cast<uint32_t*>(&t);
}

// ---------------- fused pre-kernel ----------------
// blocks [0,32): B fp16 image; blocks [32,96): T = Wlin @ Watt halves
__global__ void k_prep(const float* __restrict__ Wlin, const float* __restrict__ Watt) {
    int blk = blockIdx.x;
    if (blk < 32) {
        int t = blk * 256 + threadIdx.x;      // 0..8191
        int n = t & 511, ko = t >> 9;          // ko: 16 k-octs
        float v[8];
        #pragma unroll
        for (int j = 0; j < 8; ++j)
            v[j] = Wlin[(size_t)(ko * 8 + j) * 512 + n];
        // permuted (nblk, slot)
        int chunk = n >> 6, cc = n & 63, nhalf = cc >> 5, w32 = cc & 31;
        int jj = w32 >> 3, g = (w32 >> 1) & 3, r = w32 & 1;
        int nblk = chunk * 8 + nhalf * 4 + g;
        int nr = jj * 2 + r;
        int kblk = ko >> 1, kh = ko & 1;
        uint32_t off = (uint32_t)nblk * 2048u + (uint32_t)kblk * 256u
                     + (((uint32_t)nr * 32u + (uint32_t)kh * 16u) ^ ((nr & 4) ? 16u : 0u));
        *(uint4*)(&gWimg[off]) = make_uint4(pkh2(v[0], v[1]), pkh2(v[2], v[3]),
                                            pkh2(v[4], v[5]), pkh2(v[6], v[7]));
    } else {
        int t = (blk - 32) * 256 + threadIdx.x;   // 0..16383
        int o = t >> 3, sub = t & 7;               // 2048 outputs, 8 threads each
        int half = o >> 10, f = (o >> 3) & 127, h = o & 7;
        const float* wl = Wlin + (size_t)f * 512;
        const float* wa = Watt + (size_t)half * 512 * 8 + h;
        float acc = 0.f;
        int c0 = sub * 64;
        #pragma unroll 8
        for (int c = c0; c < c0 + 64; ++c)
            acc += wl[c] * wa[(size_t)c * 8];
        #pragma unroll
        for (int off = 4; off > 0; off >>= 1)
            acc += __shfl_xor_sync(0xffffffffu, acc, off);
        if (sub == 0) gT[half][f][h] = acc;
    }
}

// ---------------- main kernel: 256 threads, 1 batch, 3 CTAs/SM ----------------
// SMEM (bytes): A image [mblk4][kblk8][512B] @0 (16KB, fp16 single)
//               B ring 3 x 16KB @16384 (x fp32 stage [64][128]=32KB aliased buf0+buf1)
//               SS[8] @65536 ; ATT[8][64] @65600  (total 67648)
#define SM_A     0
#define SM_B     16384
#define SM_SS    65536
#define SM_ATT   65600
#define SMEM_BYTES 67648

__global__ void __launch_bounds__(256, 3)
agg_main(const float* __restrict__ x, const int* __restrict__ mask,
         float* __restrict__ out)
{
    extern __shared__ unsigned char sm[];
    const int t = threadIdx.x, w = t >> 5, lane = t & 31;
    const int b = blockIdx.x;
    const uint32_t sb = smem_u32(sm);
    float* stage = (float*)(sm + SM_B);            // aliased on B buf0+buf1
    float* attb  = (float*)(sm + SM_ATT);
    float* sS    = (float*)(sm + SM_SS);
    const float* gT0 = &gT[0][0][0];
    const float* gT1 = &gT[1][0][0];

    // ---- G0: x (32KB) into stage ----
    const float* xp = x + (size_t)b * 8192;
    #pragma unroll
    for (int i = 0; i < 8; ++i) {
        int idx = t + i * 256;
        cp_async16(sb + SM_B + idx * 16, (const char*)xp + idx * 16);
    }
    cp_commit();
    // ---- G1: chunk 0 -> buf2 (free 16KB) ----
    #pragma unroll
    for (int i = 0; i < 4; ++i) {
        int u = t + i * 256;
        cp_async16(sb + SM_B + 32768u + u * 16, &gWimg[u * 16]);
    }
    cp_commit();
    cp_wait<1>();       // x arrived
    __syncthreads();

    // ---- convert x -> fp16 A tile image (1024 tasks of 8 elems) ----
    #pragma unroll
    for (int i = 0; i < 4; ++i) {
        int idx = t + i * 256;
        int m = idx >> 4, k0 = (idx & 15) * 8;      // m 0..63
        float4 v0 = *(float4*)(stage + m * 128 + k0);
        float4 v1 = *(float4*)(stage + m * 128 + k0 + 4);
        int mblk = m >> 4, rr = m & 15, kblk = k0 >> 4, kh = (k0 >> 3) & 1;
        uint32_t off = (uint32_t)mblk * 4096u + (uint32_t)kblk * 512u
                     + (((uint32_t)rr * 32u + (uint32_t)kh * 16u) ^ ((rr & 4) ? 16u : 0u));
        *(uint4*)(sm + SM_A + off) = make_uint4(pkh2(v0.x, v0.y), pkh2(v0.z, v0.w),
                                                pkh2(v1.x, v1.y), pkh2(v1.z, v1.w));
    }

    // ---- attention logits: 512 (r,h) tasks, fp32; T read from global (L1) ----
    float dotv[2]; int rr2[2], hh2[2];
    #pragma unroll
    for (int j = 0; j < 2; ++j) {
        int idx2 = t + j * 256;
        int r = idx2 >> 3, h = idx2 & 7;
        const float* xr = stage + r * 128;
        float acc = 0.f;
        #pragma unroll 4
        for (int k = 0; k < 128; k += 4) {
            float4 xv = *(float4*)(xr + k);
            acc += xv.x * __ldg(gT1 + (k + 0) * 8 + h);
            acc += xv.y * __ldg(gT1 + (k + 1) * 8 + h);
            acc += xv.z * __ldg(gT1 + (k + 2) * 8 + h);
            acc += xv.w * __ldg(gT1 + (k + 3) * 8 + h);
        }
        dotv[j] = acc; rr2[j] = r; hh2[j] = h;
    }
    float srcv = 0.f;
    if (t < 8) {        // src term: row 0 vs T0, head = t
        const float* xr = stage;
        #pragma unroll 4
        for (int k = 0; k < 128; k += 4) {
            float4 xv = *(float4*)(xr + k);
            srcv += xv.x * __ldg(gT0 + (k + 0) * 8 + t);
            srcv += xv.y * __ldg(gT0 + (k + 1) * 8 + t);
            srcv += xv.z * __ldg(gT0 + (k + 2) * 8 + t);
            srcv += xv.w * __ldg(gT0 + (k + 3) * 8 + t);
        }
    }
    __syncthreads();    // stage fully read; A image visible
    if (t < 8) sS[t] = srcv;

    // ---- G2: chunk 1 -> buf0 (stage dead) ----
    #pragma unroll
    for (int i = 0; i < 4; ++i) {
        int u = t + i * 256;
        cp_async16(sb + SM_B + u * 16, &gWimg[16384 + u * 16]);
    }
    cp_commit();

    // ---- hoist A fragments (chunk-invariant): 32 regs ----
    const int mblk = w >> 1, nhalf = w & 1;
    const int ja = lane >> 3, ra = lane & 7;
    const int ml  = (ja & 1) * 8 + ra, kha = ja >> 1;
    const uint32_t arow = (((uint32_t)ml * 32u + (uint32_t)kha * 16u) ^ ((ml & 4) ? 16u : 0u));
    const uint32_t aad0 = sb + SM_A + (uint32_t)mblk * 4096u + arow;
    uint32_t af[8][4];
    #pragma unroll
    for (int kblk = 0; kblk < 8; ++kblk)
        LDSM_X4(af[kblk], aad0 + (uint32_t)kblk * 512u);
    __syncthreads();    // sS visible

    // ---- logits -> attb ----
    #pragma unroll
    for (int j = 0; j < 2; ++j) {
        int n = rr2[j];
        float v = sS[hh2[j]] + dotv[j];
        v = (v >= 0.f) ? v : 0.2f * v;
        attb[hh2[j] * 64 + n] = v;
    }
    __syncthreads();

    // ---- softmax: warp w -> head w ----
    {
        int m0 = mask[b * 64 + lane];
        int m1 = mask[b * 64 + lane + 32];
        float v0 = attb[w * 64 + lane]      + (m0 == 0 ? -1e9f : 0.f);
        float v1 = attb[w * 64 + lane + 32] + (m1 == 0 ? -1e9f : 0.f);
        float mx = fmaxf(v0, v1);
        #pragma unroll
        for (int o = 16; o > 0; o >>= 1) mx = fmaxf(mx, __shfl_xor_sync(0xffffffffu, mx, o));
        float e0 = __expf(v0 - mx), e1 = __expf(v1 - mx);
        float sum = e0 + e1;
        #pragma unroll
        for (int o = 16; o > 0; o >>= 1) sum += __shfl_xor_sync(0xffffffffu, sum, o);
        float inv = 1.f / sum;
        attb[w * 64 + lane]      = e0 * inv;
        attb[w * 64 + lane + 32] = e1 * inv;
    }

    // ---- B addressing + epilogue lane mapping (permuted columns) ----
    const int nbo = (ja >> 1), khb = ja & 1;
    const uint32_t brow = (((uint32_t)ra * 32u + (uint32_t)khb * 16u) ^ ((ra & 4) ? 16u : 0u));
    const int er = lane >> 2, jj = lane & 3;
    const int ns0 = mblk * 16 + er, ns1 = ns0 + 8;
    float* ob0 = out + ((size_t)b * 64 + ns0) * 512 + nhalf * 32 + jj * 8;
    float* ob1 = out + ((size_t)b * 64 + ns1) * 512 + nhalf * 32 + jj * 8;

    // ---- mainloop: 8 chunks (chunk == head), 3-stage B ring, 1 sync/chunk ----
    // chunk m in buf (m+2)%3; iter c issues chunk c+2 into buf (c+1)%3
    for (int c = 0; c < 8; ++c) {
        if (c < 7) cp_wait<1>(); else cp_wait<0>();   // chunk c arrived
        __syncthreads();
        if (c + 2 <= 7) {
            uint32_t dst = sb + SM_B + (uint32_t)((c + 1) % 3) * 16384u;
            #pragma unroll
            for (int i = 0; i < 4; ++i) {
                int u = t + i * 256;
                cp_async16(dst + u * 16, &gWimg[(c + 2) * 16384 + u * 16]);
            }
            cp_commit();
        }

        const uint32_t bbase = sb + SM_B + (uint32_t)((c + 2) % 3) * 16384u;
        float acc[16];
        #pragma unroll
        for (int i = 0; i < 16; ++i) acc[i] = 0.f;

        // depth-1 pipelined B stream: flat iter i = kblk*2 + ng
        uint32_t bh[2][4];
        {
            uint32_t bad = bbase + (uint32_t)(nhalf * 4 + nbo) * 2048u + brow;
            LDSM_X4(bh[0], bad);
        }
        #pragma unroll
        for (int i = 0; i < 16; ++i) {
            const int cur = i & 1, nxt = cur ^ 1;
            if (i < 15) {
                int kn = i + 1;
                uint32_t bad = bbase
                    + (uint32_t)(nhalf * 4 + (kn & 1) * 2 + nbo) * 2048u
                    + (uint32_t)(kn >> 1) * 256u + brow;
                LDSM_X4(bh[nxt], bad);
            }
            const int kblk = i >> 1, go = (i & 1) * 8;
            mmaf16(acc + go + 0, af[kblk], bh[cur][0], bh[cur][1]);
            mmaf16(acc + go + 4, af[kblk], bh[cur][2], bh[cur][3]);
        }

        // ---- epilogue: permuted cols => 8 contiguous floats per thread per row ----
        float sc0 = attb[c * 64 + ns0];
        float sc1 = attb[c * 64 + ns1];
        float* o0 = ob0 + c * 64;
        float* o1 = ob1 + c * 64;
        float4 v00 = make_float4(fmaxf(acc[0]  * sc0, 0.f), fmaxf(acc[1]  * sc0, 0.f),
                                 fmaxf(acc[4]  * sc0, 0.f), fmaxf(acc[5]  * sc0, 0.f));
        float4 v01 = make_float4(fmaxf(acc[8]  * sc0, 0.f), fmaxf(acc[9]  * sc0, 0.f),
                                 fmaxf(acc[12] * sc0, 0.f), fmaxf(acc[13] * sc0, 0.f));
        float4 v10 = make_float4(fmaxf(acc[2]  * sc1, 0.f), fmaxf(acc[3]  * sc1, 0.f),
                                 fmaxf(acc[6]  * sc1, 0.f), fmaxf(acc[7]  * sc1, 0.f));
        float4 v11 = make_float4(fmaxf(acc[10] * sc1, 0.f), fmaxf(acc[11] * sc1, 0.f),
                                 fmaxf(acc[14] * sc1, 0.f), fmaxf(acc[15] * sc1, 0.f));
        *(float4*)(o0)     = v00;
        *(float4*)(o0 + 4) = v01;
        *(float4*)(o1)     = v10;
        *(float4*)(o1 + 4) = v11;
    }
}

// ---------------- launch ----------------
extern "C" void kernel_launch(void* const* d_in, const int* in_sizes, int n_in,
                              void* d_out, int out_size)
{
    const float* x    = (const float*)d_in[0];
    const float* Wlin = (const float*)d_in[1];
    const float* Watt = (const float*)d_in[2];
    const int*   mk   = (const int*)d_in[3];
    float*       out  = (float*)d_out;

    k_prep<<<96, 256>>>(Wlin, Watt);

    cudaFuncSetAttribute(agg_main, cudaFuncAttributeMaxDynamicSharedMemorySize, SMEM_BYTES);
    agg_main<<<BATCH, 256, SMEM_BYTES>>>(x, mk, out);
}